// round 5
// baseline (speedup 1.0000x reference)
#include <cuda_runtime.h>
#include <cuda_bf16.h>
#include <cuda_fp16.h>
#include <cstdint>

// Problem constants (fixed by the dataset)
#define N_NODES 50000
#define N_EDGES 800000
#define DIM     128
#define OUTD    12
#define CAP     128          // per-node in-edge bucket capacity (Poisson(16) degree)

// ---------------------------------------------------------------------------
// Device scratch (no allocations allowed)
// ---------------------------------------------------------------------------
__device__ __half g_H[N_NODES * DIM];       // GEMM output (dinv-scaled), fp16
__device__ float  g_A[N_NODES * DIM];       // ping
__device__ float  g_B[N_NODES * DIM];       // pong
__device__ float  g_Wt[3 * DIM * DIM];      // transposed weights (B operands)
__device__ float  g_dinv[N_NODES];
__device__ int    g_cnt[N_NODES];
__device__ int    g_bucket[N_NODES * CAP];  // in-edge src lists per dst

// ---------------------------------------------------------------------------
// CSR-bucket build
// ---------------------------------------------------------------------------
__global__ void k_zero_cnt(int* cnt, int n) {
    int i = blockIdx.x * blockDim.x + threadIdx.x;
    if (i < n) cnt[i] = 0;
}

__global__ void k_fill(const int* __restrict__ src, const int* __restrict__ dst,
                       int* cnt, int* bucket, int E) {
    int e = blockIdx.x * blockDim.x + threadIdx.x;
    if (e >= E) return;
    int d = dst[e];
    int pos = atomicAdd(&cnt[d], 1);
    if (pos < CAP) bucket[(size_t)d * CAP + pos] = src[e];
}

__global__ void k_dinv(const int* __restrict__ cnt, float* dinv, int n) {
    int i = blockIdx.x * blockDim.x + threadIdx.x;
    if (i < n) dinv[i] = rsqrtf(1.0f + (float)cnt[i]);   // +1 = self loop
}

// ---------------------------------------------------------------------------
// Fused weight transpose: Wt[z][c][k] = Wz[k][c]  (B operand needs [N][K])
// ---------------------------------------------------------------------------
__global__ void k_transpose3(const float* __restrict__ W1, const float* __restrict__ W2,
                             const float* __restrict__ W3, float* __restrict__ Wt) {
    __shared__ float tile[32][33];
    const float* W = (blockIdx.z == 0) ? W1 : (blockIdx.z == 1) ? W2 : W3;
    float* dst = Wt + (size_t)blockIdx.z * DIM * DIM;
    int x = blockIdx.x * 32 + threadIdx.x;
    int y = blockIdx.y * 32 + threadIdx.y;
#pragma unroll
    for (int j = 0; j < 32; j += 8)
        tile[threadIdx.y + j][threadIdx.x] = W[(y + j) * DIM + x];
    __syncthreads();
    x = blockIdx.y * 32 + threadIdx.x;
    y = blockIdx.x * 32 + threadIdx.y;
#pragma unroll
    for (int j = 0; j < 32; j += 8)
        dst[(y + j) * DIM + x] = tile[threadIdx.x][threadIdx.y + j];
}

// ---------------------------------------------------------------------------
// tf32 tensor-core GEMM (mma.sync.m16n8k8): H'[r] = fp16(dinv[r] * (X[r] @ W)).
// CTA: 128 rows x 128 cols x K=128. 8 warps in 4x2 grid; warp tile 32x64.
// ---------------------------------------------------------------------------
#define SLD 132                              // padded row stride (floats)
#define GEMM_SMEM_BYTES (2 * DIM * SLD * 4)  // 135168 B

__device__ __forceinline__ uint32_t f2tf32(float f) {
    uint32_t u;
    asm("cvt.rna.tf32.f32 %0, %1;" : "=r"(u) : "f"(f));
    return u;
}

__device__ __forceinline__ void mma_tf32(float* d, const uint32_t* a,
                                         uint32_t b0, uint32_t b1) {
    asm volatile(
        "mma.sync.aligned.m16n8k8.row.col.f32.tf32.tf32.f32 "
        "{%0,%1,%2,%3}, {%4,%5,%6,%7}, {%8,%9}, {%0,%1,%2,%3};"
        : "+f"(d[0]), "+f"(d[1]), "+f"(d[2]), "+f"(d[3])
        : "r"(a[0]), "r"(a[1]), "r"(a[2]), "r"(a[3]), "r"(b0), "r"(b1));
}

__global__ void __launch_bounds__(256, 1) k_gemm_tc(
    const float* __restrict__ X, const float* __restrict__ Bt,
    const float* __restrict__ dinv, __half* __restrict__ H, int n) {
    extern __shared__ uint32_t smem[];
    uint32_t* Xs = smem;               // [128][SLD] tf32 bits
    uint32_t* Bs = smem + DIM * SLD;   // [128][SLD] tf32 bits (W^T: [n][k])

    const int tid  = threadIdx.x;
    const int row0 = blockIdx.x * 128;

    // Stage X tile (zero-pad past n) and W^T, converting to tf32.
    const float4* X4 = (const float4*)X;
    const float4* B4 = (const float4*)Bt;
#pragma unroll
    for (int i = 0; i < 16; i++) {
        int idx = tid + i * 256;
        int r = idx >> 5, c4 = idx & 31;
        int gr = row0 + r;
        float4 v = make_float4(0.f, 0.f, 0.f, 0.f);
        if (gr < n) v = X4[gr * 32 + c4];
        uint4 t = make_uint4(f2tf32(v.x), f2tf32(v.y), f2tf32(v.z), f2tf32(v.w));
        *(uint4*)&Xs[r * SLD + c4 * 4] = t;

        float4 w = B4[idx];
        uint4 tw = make_uint4(f2tf32(w.x), f2tf32(w.y), f2tf32(w.z), f2tf32(w.w));
        *(uint4*)&Bs[r * SLD + c4 * 4] = tw;
    }
    __syncthreads();

    const int warp = tid >> 5;
    const int lane = tid & 31;
    const int wm   = warp & 3;        // m-tile: rows wm*32 .. wm*32+31
    const int wn   = warp >> 2;       // n-tile: cols wn*64 .. wn*64+63
    const int g    = lane >> 2;       // group id (0..7)
    const int tg   = lane & 3;        // thread-in-group (0..3)

    float acc[2][8][4];
#pragma unroll
    for (int mt = 0; mt < 2; mt++)
#pragma unroll
        for (int nt = 0; nt < 8; nt++)
#pragma unroll
            for (int q = 0; q < 4; q++) acc[mt][nt][q] = 0.f;

#pragma unroll
    for (int ks = 0; ks < 16; ks++) {
        const int k0 = ks * 8;
        uint32_t a[2][4];
#pragma unroll
        for (int mt = 0; mt < 2; mt++) {
            int r0 = wm * 32 + mt * 16;
            a[mt][0] = Xs[(r0 + g) * SLD + k0 + tg];
            a[mt][1] = Xs[(r0 + 8 + g) * SLD + k0 + tg];
            a[mt][2] = Xs[(r0 + g) * SLD + k0 + tg + 4];
            a[mt][3] = Xs[(r0 + 8 + g) * SLD + k0 + tg + 4];
        }
#pragma unroll
        for (int nt = 0; nt < 8; nt++) {
            int c0 = wn * 64 + nt * 8;
            uint32_t b0 = Bs[(c0 + g) * SLD + k0 + tg];
            uint32_t b1 = Bs[(c0 + g) * SLD + k0 + tg + 4];
            mma_tf32(acc[0][nt], a[0], b0, b1);
            mma_tf32(acc[1][nt], a[1], b0, b1);
        }
    }

    // Epilogue: scale by dinv[row], convert to fp16, half2 stores.
#pragma unroll
    for (int mt = 0; mt < 2; mt++) {
        int r0 = row0 + wm * 32 + mt * 16 + g;
        int r1 = r0 + 8;
        float dv0 = (r0 < n) ? dinv[r0] : 0.f;
        float dv1 = (r1 < n) ? dinv[r1] : 0.f;
#pragma unroll
        for (int nt = 0; nt < 8; nt++) {
            int col = wn * 64 + nt * 8 + tg * 2;
            if (r0 < n) {
                __half2 h = __floats2half2_rn(acc[mt][nt][0] * dv0, acc[mt][nt][1] * dv0);
                *(__half2*)&H[(size_t)r0 * DIM + col] = h;
            }
            if (r1 < n) {
                __half2 h = __floats2half2_rn(acc[mt][nt][2] * dv1, acc[mt][nt][3] * dv1);
                *(__half2*)&H[(size_t)r1 * DIM + col] = h;
            }
        }
    }
}

// ---------------------------------------------------------------------------
// Pull aggregation: one warp per destination node, fp16 gather / fp32 accum.
// OUT[v] = relu(bias + dinv[v] * (H'[v] + sum_{s in in(v)} H'[s]))
// ---------------------------------------------------------------------------
__global__ void k_pull(const int* __restrict__ bucket, const int* __restrict__ cnt,
                       const float* __restrict__ dinv, const __half* __restrict__ H,
                       const float* __restrict__ bias, float* __restrict__ OUT, int n) {
    int warp = (blockIdx.x * blockDim.x + threadIdx.x) >> 5;
    int lane = threadIdx.x & 31;
    if (warp >= n) return;
    const int v   = warp;
    int deg = cnt[v];
    if (deg > CAP) deg = CAP;
    const int* bk = bucket + (size_t)v * CAP;
    const uint2* H2 = (const uint2*)H;   // 4 halfs per uint2; 32 uint2 per row

    float4 acc0, acc1 = make_float4(0.f, 0.f, 0.f, 0.f);
    {   // self-loop term
        uint2 raw = H2[(size_t)v * 32 + lane];
        float2 lo = __half22float2(*(__half2*)&raw.x);
        float2 hi = __half22float2(*(__half2*)&raw.y);
        acc0 = make_float4(lo.x, lo.y, hi.x, hi.y);
    }

    for (int base = 0; base < deg; base += 32) {
        int m = deg - base; if (m > 32) m = 32;
        int myS = (lane < m) ? bk[base + lane] : 0;
        int i = 0;
        for (; i + 2 <= m; i += 2) {
            int s0 = __shfl_sync(0xffffffff, myS, i);
            int s1 = __shfl_sync(0xffffffff, myS, i + 1);
            uint2 r0 = H2[(size_t)s0 * 32 + lane];
            uint2 r1 = H2[(size_t)s1 * 32 + lane];
            float2 a = __half22float2(*(__half2*)&r0.x);
            float2 b = __half22float2(*(__half2*)&r0.y);
            acc0.x += a.x; acc0.y += a.y; acc0.z += b.x; acc0.w += b.y;
            float2 c = __half22float2(*(__half2*)&r1.x);
            float2 d = __half22float2(*(__half2*)&r1.y);
            acc1.x += c.x; acc1.y += c.y; acc1.z += d.x; acc1.w += d.y;
        }
        if (i < m) {
            int s0 = __shfl_sync(0xffffffff, myS, i);
            uint2 r0 = H2[(size_t)s0 * 32 + lane];
            float2 a = __half22float2(*(__half2*)&r0.x);
            float2 b = __half22float2(*(__half2*)&r0.y);
            acc0.x += a.x; acc0.y += a.y; acc0.z += b.x; acc0.w += b.y;
        }
    }

    float dv = dinv[v];
    const float4 bb = ((const float4*)bias)[lane];
    float4 o;
    o.x = fmaxf(fmaf((acc0.x + acc1.x), dv, bb.x), 0.f);
    o.y = fmaxf(fmaf((acc0.y + acc1.y), dv, bb.y), 0.f);
    o.z = fmaxf(fmaf((acc0.z + acc1.z), dv, bb.z), 0.f);
    o.w = fmaxf(fmaf((acc0.w + acc1.w), dv, bb.w), 0.f);
    ((float4*)OUT)[(size_t)v * 32 + lane] = o;
}

// ---------------------------------------------------------------------------
// Regressor: pred[t] = A[target[t]] @ Wr[128 x 12] + br   (A already relu'd)
// ---------------------------------------------------------------------------
__global__ void k_regress(const float* __restrict__ H, const int* __restrict__ tgt,
                          const float* __restrict__ Wr, const float* __restrict__ br,
                          float* __restrict__ out, int ntgt) {
    __shared__ float Wrs[DIM * OUTD];
    __shared__ float brs[OUTD];
    int tid = threadIdx.x;
    for (int i = tid; i < DIM * OUTD; i += blockDim.x) Wrs[i] = Wr[i];
    if (tid < OUTD) brs[tid] = br[tid];
    __syncthreads();

    int warp = (blockIdx.x * blockDim.x + tid) >> 5;
    int lane = tid & 31;
    if (warp >= ntgt) return;
    int t = tgt[warp];
    float4 v = ((const float4*)H)[(size_t)t * 32 + lane];
    int k0 = lane * 4;
#pragma unroll
    for (int o = 0; o < OUTD; o++) {
        float p = v.x * Wrs[(k0 + 0) * OUTD + o]
                + v.y * Wrs[(k0 + 1) * OUTD + o]
                + v.z * Wrs[(k0 + 2) * OUTD + o]
                + v.w * Wrs[(k0 + 3) * OUTD + o];
#pragma unroll
        for (int off = 16; off > 0; off >>= 1)
            p += __shfl_xor_sync(0xffffffff, p, off);
        if (lane == 0) out[warp * OUTD + o] = p + brs[o];
    }
}

// ---------------------------------------------------------------------------
// Launch
// ---------------------------------------------------------------------------
extern "C" void kernel_launch(void* const* d_in, const int* in_sizes, int n_in,
                              void* d_out, int out_size) {
    const float* x    = (const float*)d_in[0];
    const int*   ei   = (const int*)d_in[1];
    const int*   tgt  = (const int*)d_in[2];
    const float* W1   = (const float*)d_in[3];
    const float* b1   = (const float*)d_in[4];
    const float* W2   = (const float*)d_in[5];
    const float* b2   = (const float*)d_in[6];
    const float* W3   = (const float*)d_in[7];
    const float* b3   = (const float*)d_in[8];
    const float* Wr   = (const float*)d_in[9];
    const float* br   = (const float*)d_in[10];
    float* out = (float*)d_out;

    const int n    = in_sizes[0] / DIM;
    const int E    = in_sizes[1] / 2;
    const int ntgt = in_sizes[2];
    const int* src = ei;
    const int* dst = ei + E;

    __half* H;
    float *A, *B, *Wt, *dinv;
    int *cnt, *bucket;
    cudaGetSymbolAddress((void**)&H,      g_H);
    cudaGetSymbolAddress((void**)&A,      g_A);
    cudaGetSymbolAddress((void**)&B,      g_B);
    cudaGetSymbolAddress((void**)&Wt,     g_Wt);
    cudaGetSymbolAddress((void**)&dinv,   g_dinv);
    cudaGetSymbolAddress((void**)&cnt,    g_cnt);
    cudaGetSymbolAddress((void**)&bucket, g_bucket);

    cudaFuncSetAttribute(k_gemm_tc, cudaFuncAttributeMaxDynamicSharedMemorySize,
                         GEMM_SMEM_BYTES);

    const int TPB = 256;
    const int nBlk    = (n + TPB - 1) / TPB;
    const int eBlk    = (E + TPB - 1) / TPB;
    const int gemmBlk = (n + 127) / 128;
    const int pullBlk = ((n * 32) + TPB - 1) / TPB;
    const int regBlk  = ((ntgt * 32) + TPB - 1) / TPB;

    // Build in-edge buckets + dinv (same for all 3 convs)
    k_zero_cnt<<<nBlk, TPB>>>(cnt, n);
    k_fill<<<eBlk, TPB>>>(src, dst, cnt, bucket, E);
    k_dinv<<<nBlk, TPB>>>(cnt, dinv, n);

    // Transpose all weights in one launch
    k_transpose3<<<dim3(4, 4, 3), dim3(32, 8)>>>(W1, W2, W3, Wt);

    // Conv 1: x -> A
    k_gemm_tc<<<gemmBlk, 256, GEMM_SMEM_BYTES>>>(x, Wt, dinv, H, n);
    k_pull<<<pullBlk, TPB>>>(bucket, cnt, dinv, H, b1, A, n);

    // Conv 2: A -> B
    k_gemm_tc<<<gemmBlk, 256, GEMM_SMEM_BYTES>>>(A, Wt + DIM * DIM, dinv, H, n);
    k_pull<<<pullBlk, TPB>>>(bucket, cnt, dinv, H, b2, B, n);

    // Conv 3: B -> A
    k_gemm_tc<<<gemmBlk, 256, GEMM_SMEM_BYTES>>>(B, Wt + 2 * DIM * DIM, dinv, H, n);
    k_pull<<<pullBlk, TPB>>>(bucket, cnt, dinv, H, b3, A, n);

    // Regressor on targets
    k_regress<<<regBlk, TPB>>>(A, tgt, Wr, br, out, ntgt);
}

// round 7
// speedup vs baseline: 1.0308x; 1.0308x over previous
#include <cuda_runtime.h>
#include <cuda_bf16.h>
#include <cstdint>

// Problem constants (fixed by the dataset)
#define N_NODES 50000
#define N_EDGES 800000
#define DIM     128
#define OUTD    12
#define CAP     128          // per-node in-edge bucket capacity (Poisson(16) degree)

// ---------------------------------------------------------------------------
// Device scratch (no allocations allowed)
// ---------------------------------------------------------------------------
__device__ float g_H[N_NODES * DIM];        // GEMM output, pre-scaled by dinv
__device__ float g_A[N_NODES * DIM];        // ping (tf32-rounded activations)
__device__ float g_B[N_NODES * DIM];        // pong
__device__ float g_Wt[3 * DIM * DIM];       // transposed + tf32-rounded weights
__device__ float g_dinv[N_NODES];
__device__ int   g_cnt[N_NODES];
__device__ int   g_bucket[N_NODES * CAP];   // in-edge src lists per dst

__device__ __forceinline__ uint32_t f2tf32(float f) {
    uint32_t u;
    asm("cvt.rna.tf32.f32 %0, %1;" : "=r"(u) : "f"(f));
    return u;
}

// ---------------------------------------------------------------------------
// CSR-bucket build
// ---------------------------------------------------------------------------
__global__ void k_zero_cnt(int* cnt, int n) {
    int i = blockIdx.x * blockDim.x + threadIdx.x;
    if (i < n) cnt[i] = 0;
}

__global__ void k_fill(const int* __restrict__ src, const int* __restrict__ dst,
                       int* cnt, int* bucket, int E) {
    int e = blockIdx.x * blockDim.x + threadIdx.x;
    if (e >= E) return;
    int d = dst[e];
    int pos = atomicAdd(&cnt[d], 1);
    if (pos < CAP) bucket[(size_t)d * CAP + pos] = src[e];
}

__global__ void k_dinv(const int* __restrict__ cnt, float* dinv, int n) {
    int i = blockIdx.x * blockDim.x + threadIdx.x;
    if (i < n) dinv[i] = rsqrtf(1.0f + (float)cnt[i]);   // +1 = self loop
}

// ---------------------------------------------------------------------------
// Fused weight transpose + tf32 RNA rounding: Wt[z][c][k] = rna(Wz[k][c])
// ---------------------------------------------------------------------------
__global__ void k_transpose3(const float* __restrict__ W1, const float* __restrict__ W2,
                             const float* __restrict__ W3, float* __restrict__ Wt) {
    __shared__ float tile[32][33];
    const float* W = (blockIdx.z == 0) ? W1 : (blockIdx.z == 1) ? W2 : W3;
    float* dst = Wt + (size_t)blockIdx.z * DIM * DIM;
    int x = blockIdx.x * 32 + threadIdx.x;
    int y = blockIdx.y * 32 + threadIdx.y;
#pragma unroll
    for (int j = 0; j < 32; j += 8)
        tile[threadIdx.y + j][threadIdx.x] = W[(y + j) * DIM + x];
    __syncthreads();
    x = blockIdx.y * 32 + threadIdx.x;
    y = blockIdx.x * 32 + threadIdx.y;
#pragma unroll
    for (int j = 0; j < 32; j += 8)
        dst[(y + j) * DIM + x] = __uint_as_float(f2tf32(tile[threadIdx.x][threadIdx.y + j]));
}

// ---------------------------------------------------------------------------
// tf32 tensor-core GEMM with cp.async pipelined staging.
// H'[r] = dinv[r] * (X[r] @ W).  CTA: 128 rows x 128 cols; K in 4 chunks of 32,
// double-buffered.  8 warps in 4x2 grid; warp tile 32x64.
// CVTA=true: RNA-round A fragments in-register (layer 1, raw input X).
// Layers 2/3 read activations already RNA-rounded by k_pull; W pre-rounded.
// ---------------------------------------------------------------------------
#define CLD 36                      // chunk row stride (floats): 32 + 4 pad
#define CHUNK_U32 (DIM * CLD)       // 4608 u32 per matrix per buffer
#define BUF_U32   (2 * CHUNK_U32)   // X + B chunk per buffer
#define GEMM_SMEM_BYTES (2 * BUF_U32 * 4)   // 73728 B

__device__ __forceinline__ uint32_t smem_u32(const void* p) {
    uint32_t a;
    asm("{ .reg .u64 t; cvta.to.shared.u64 t, %1; cvt.u32.u64 %0, t; }" : "=r"(a) : "l"(p));
    return a;
}

__device__ __forceinline__ void mma_tf32(float* d, const uint32_t* a,
                                         uint32_t b0, uint32_t b1) {
    asm volatile(
        "mma.sync.aligned.m16n8k8.row.col.f32.tf32.tf32.f32 "
        "{%0,%1,%2,%3}, {%4,%5,%6,%7}, {%8,%9}, {%0,%1,%2,%3};"
        : "+f"(d[0]), "+f"(d[1]), "+f"(d[2]), "+f"(d[3])
        : "r"(a[0]), "r"(a[1]), "r"(a[2]), "r"(a[3]), "r"(b0), "r"(b1));
}

template <bool CVTA>
__global__ void __launch_bounds__(256, 1) k_gemm_tc(
    const float* __restrict__ X, const float* __restrict__ Bt,
    const float* __restrict__ dinv, float* __restrict__ H, int n) {
    extern __shared__ uint32_t smem[];
    const int tid  = threadIdx.x;
    const int row0 = blockIdx.x * 128;
    const uint32_t sbase = smem_u32(smem);

    // Stage one K-chunk (X cols c*32..c*32+31, B cols same) into buffer c&1.
    auto stage = [&](int c) {
        const int buf = c & 1;
        const uint32_t xb = sbase + (uint32_t)buf * (BUF_U32 * 4);
        const uint32_t bb = xb + CHUNK_U32 * 4;
        const float4* X4 = (const float4*)X;
        const float4* B4 = (const float4*)Bt;
#pragma unroll
        for (int i = 0; i < 4; i++) {
            int idx = tid + i * 256;          // 1024 float4s per matrix chunk
            int r = idx >> 3, c4 = idx & 7;   // 128 rows x 8 float4
            uint32_t off = (uint32_t)(r * CLD + c4 * 4) * 4;
            const float4* xsrc = X4 + ((size_t)(row0 + r) * 32 + c * 8 + c4);
            int vs = (row0 + r < n) ? 16 : 0;
            asm volatile("cp.async.cg.shared.global [%0], [%1], 16, %2;"
                         :: "r"(xb + off), "l"(xsrc), "r"(vs));
            const float4* bsrc = B4 + ((size_t)r * 32 + c * 8 + c4);
            asm volatile("cp.async.cg.shared.global [%0], [%1], 16;"
                         :: "r"(bb + off), "l"(bsrc));
        }
        asm volatile("cp.async.commit_group;" ::: "memory");
    };

    stage(0);
    stage(1);

    const int warp = tid >> 5;
    const int lane = tid & 31;
    const int wm   = warp & 3;        // m-tile: rows wm*32 .. wm*32+31
    const int wn   = warp >> 2;       // n-tile: cols wn*64 .. wn*64+63
    const int g    = lane >> 2;       // group id (0..7)
    const int tg   = lane & 3;        // thread-in-group (0..3)

    float acc[2][8][4];
#pragma unroll
    for (int mt = 0; mt < 2; mt++)
#pragma unroll
        for (int nt = 0; nt < 8; nt++)
#pragma unroll
            for (int q = 0; q < 4; q++) acc[mt][nt][q] = 0.f;

#pragma unroll
    for (int c = 0; c < 4; c++) {
        if (c < 3) asm volatile("cp.async.wait_group 1;" ::: "memory");
        else       asm volatile("cp.async.wait_group 0;" ::: "memory");
        __syncthreads();

        const uint32_t* Xs = smem + (c & 1) * BUF_U32;
        const uint32_t* Bs = Xs + CHUNK_U32;

#pragma unroll
        for (int ks = 0; ks < 4; ks++) {
            const int k0 = ks * 8;
            uint32_t a[2][4];
#pragma unroll
            for (int mt = 0; mt < 2; mt++) {
                int r0 = wm * 32 + mt * 16;
                a[mt][0] = Xs[(r0 + g) * CLD + k0 + tg];
                a[mt][1] = Xs[(r0 + 8 + g) * CLD + k0 + tg];
                a[mt][2] = Xs[(r0 + g) * CLD + k0 + tg + 4];
                a[mt][3] = Xs[(r0 + 8 + g) * CLD + k0 + tg + 4];
                if (CVTA) {
#pragma unroll
                    for (int q = 0; q < 4; q++)
                        a[mt][q] = f2tf32(__uint_as_float(a[mt][q]));
                }
            }
#pragma unroll
            for (int nt = 0; nt < 8; nt++) {
                int c0 = wn * 64 + nt * 8;
                uint32_t b0 = Bs[(c0 + g) * CLD + k0 + tg];
                uint32_t b1 = Bs[(c0 + g) * CLD + k0 + tg + 4];
                mma_tf32(acc[0][nt], a[0], b0, b1);
                mma_tf32(acc[1][nt], a[1], b0, b1);
            }
        }
        __syncthreads();
        if (c + 2 < 4) stage(c + 2);
    }

    // Epilogue: scale by dinv[row], float2 stores.
#pragma unroll
    for (int mt = 0; mt < 2; mt++) {
        int r0 = row0 + wm * 32 + mt * 16 + g;
        int r1 = r0 + 8;
        float dv0 = (r0 < n) ? dinv[r0] : 0.f;
        float dv1 = (r1 < n) ? dinv[r1] : 0.f;
#pragma unroll
        for (int nt = 0; nt < 8; nt++) {
            int col = wn * 64 + nt * 8 + tg * 2;
            if (r0 < n) {
                float2 o = make_float2(acc[mt][nt][0] * dv0, acc[mt][nt][1] * dv0);
                *(float2*)&H[(size_t)r0 * DIM + col] = o;
            }
            if (r1 < n) {
                float2 o = make_float2(acc[mt][nt][2] * dv1, acc[mt][nt][3] * dv1);
                *(float2*)&H[(size_t)r1 * DIM + col] = o;
            }
        }
    }
}

// ---------------------------------------------------------------------------
// Pull aggregation: one warp per destination node, fp32, 4-way ILP.
// OUT[v] = rna_tf32(relu(bias + dinv[v] * (H'[v] + sum_{s in in(v)} H'[s])))
// Output pre-rounded so the next GEMM can stage raw bits via cp.async.
// ---------------------------------------------------------------------------
__global__ void k_pull(const int* __restrict__ bucket, const int* __restrict__ cnt,
                       const float* __restrict__ dinv, const float* __restrict__ H,
                       const float* __restrict__ bias, float* __restrict__ OUT, int n) {
    int warp = (blockIdx.x * blockDim.x + threadIdx.x) >> 5;
    int lane = threadIdx.x & 31;
    if (warp >= n) return;
    const int v   = warp;
    int deg = cnt[v];
    if (deg > CAP) deg = CAP;
    const int* bk = bucket + (size_t)v * CAP;
    const float4* H4 = (const float4*)H;

    float4 acc0 = H4[(size_t)v * 32 + lane];   // self-loop term
    float4 acc1 = make_float4(0.f, 0.f, 0.f, 0.f);
    float4 acc2 = make_float4(0.f, 0.f, 0.f, 0.f);
    float4 acc3 = make_float4(0.f, 0.f, 0.f, 0.f);

    for (int base = 0; base < deg; base += 32) {
        int m = deg - base; if (m > 32) m = 32;
        int myS = (lane < m) ? bk[base + lane] : 0;
        int i = 0;
        for (; i + 4 <= m; i += 4) {
            int s0 = __shfl_sync(0xffffffff, myS, i);
            int s1 = __shfl_sync(0xffffffff, myS, i + 1);
            int s2 = __shfl_sync(0xffffffff, myS, i + 2);
            int s3 = __shfl_sync(0xffffffff, myS, i + 3);
            float4 h0 = H4[(size_t)s0 * 32 + lane];
            float4 h1 = H4[(size_t)s1 * 32 + lane];
            float4 h2 = H4[(size_t)s2 * 32 + lane];
            float4 h3 = H4[(size_t)s3 * 32 + lane];
            acc0.x += h0.x; acc0.y += h0.y; acc0.z += h0.z; acc0.w += h0.w;
            acc1.x += h1.x; acc1.y += h1.y; acc1.z += h1.z; acc1.w += h1.w;
            acc2.x += h2.x; acc2.y += h2.y; acc2.z += h2.z; acc2.w += h2.w;
            acc3.x += h3.x; acc3.y += h3.y; acc3.z += h3.z; acc3.w += h3.w;
        }
        for (; i < m; i++) {
            int s0 = __shfl_sync(0xffffffff, myS, i);
            float4 h0 = H4[(size_t)s0 * 32 + lane];
            acc0.x += h0.x; acc0.y += h0.y; acc0.z += h0.z; acc0.w += h0.w;
        }
    }

    float dv = dinv[v];
    const float4 bb = ((const float4*)bias)[lane];
    float sx = (acc0.x + acc1.x) + (acc2.x + acc3.x);
    float sy = (acc0.y + acc1.y) + (acc2.y + acc3.y);
    float sz = (acc0.z + acc1.z) + (acc2.z + acc3.z);
    float sw = (acc0.w + acc1.w) + (acc2.w + acc3.w);
    float4 o;
    o.x = __uint_as_float(f2tf32(fmaxf(fmaf(sx, dv, bb.x), 0.f)));
    o.y = __uint_as_float(f2tf32(fmaxf(fmaf(sy, dv, bb.y), 0.f)));
    o.z = __uint_as_float(f2tf32(fmaxf(fmaf(sz, dv, bb.z), 0.f)));
    o.w = __uint_as_float(f2tf32(fmaxf(fmaf(sw, dv, bb.w), 0.f)));
    ((float4*)OUT)[(size_t)v * 32 + lane] = o;
}

// ---------------------------------------------------------------------------
// Regressor: pred[t] = A[target[t]] @ Wr[128 x 12] + br   (A already relu'd)
// ---------------------------------------------------------------------------
__global__ void k_regress(const float* __restrict__ H, const int* __restrict__ tgt,
                          const float* __restrict__ Wr, const float* __restrict__ br,
                          float* __restrict__ out, int ntgt) {
    __shared__ float Wrs[DIM * OUTD];
    __shared__ float brs[OUTD];
    int tid = threadIdx.x;
    for (int i = tid; i < DIM * OUTD; i += blockDim.x) Wrs[i] = Wr[i];
    if (tid < OUTD) brs[tid] = br[tid];
    __syncthreads();

    int warp = (blockIdx.x * blockDim.x + tid) >> 5;
    int lane = tid & 31;
    if (warp >= ntgt) return;
    int t = tgt[warp];
    float4 v = ((const float4*)H)[(size_t)t * 32 + lane];
    int k0 = lane * 4;
#pragma unroll
    for (int o = 0; o < OUTD; o++) {
        float p = v.x * Wrs[(k0 + 0) * OUTD + o]
                + v.y * Wrs[(k0 + 1) * OUTD + o]
                + v.z * Wrs[(k0 + 2) * OUTD + o]
                + v.w * Wrs[(k0 + 3) * OUTD + o];
#pragma unroll
        for (int off = 16; off > 0; off >>= 1)
            p += __shfl_xor_sync(0xffffffff, p, off);
        if (lane == 0) out[warp * OUTD + o] = p + brs[o];
    }
}

// ---------------------------------------------------------------------------
// Launch
// ---------------------------------------------------------------------------
extern "C" void kernel_launch(void* const* d_in, const int* in_sizes, int n_in,
                              void* d_out, int out_size) {
    const float* x    = (const float*)d_in[0];
    const int*   ei   = (const int*)d_in[1];
    const int*   tgt  = (const int*)d_in[2];
    const float* W1   = (const float*)d_in[3];
    const float* b1   = (const float*)d_in[4];
    const float* W2   = (const float*)d_in[5];
    const float* b2   = (const float*)d_in[6];
    const float* W3   = (const float*)d_in[7];
    const float* b3   = (const float*)d_in[8];
    const float* Wr   = (const float*)d_in[9];
    const float* br   = (const float*)d_in[10];
    float* out = (float*)d_out;

    const int n    = in_sizes[0] / DIM;
    const int E    = in_sizes[1] / 2;
    const int ntgt = in_sizes[2];
    const int* src = ei;
    const int* dst = ei + E;

    float *H, *A, *B, *Wt, *dinv;
    int *cnt, *bucket;
    cudaGetSymbolAddress((void**)&H,      g_H);
    cudaGetSymbolAddress((void**)&A,      g_A);
    cudaGetSymbolAddress((void**)&B,      g_B);
    cudaGetSymbolAddress((void**)&Wt,     g_Wt);
    cudaGetSymbolAddress((void**)&dinv,   g_dinv);
    cudaGetSymbolAddress((void**)&cnt,    g_cnt);
    cudaGetSymbolAddress((void**)&bucket, g_bucket);

    cudaFuncSetAttribute(k_gemm_tc<true>, cudaFuncAttributeMaxDynamicSharedMemorySize,
                         GEMM_SMEM_BYTES);
    cudaFuncSetAttribute(k_gemm_tc<false>, cudaFuncAttributeMaxDynamicSharedMemorySize,
                         GEMM_SMEM_BYTES);

    const int TPB = 256;
    const int nBlk    = (n + TPB - 1) / TPB;
    const int eBlk    = (E + TPB - 1) / TPB;
    const int gemmBlk = (n + 127) / 128;
    const int pullBlk = ((n * 32) + TPB - 1) / TPB;
    const int regBlk  = ((ntgt * 32) + TPB - 1) / TPB;

    // Build in-edge buckets + dinv (same for all 3 convs)
    k_zero_cnt<<<nBlk, TPB>>>(cnt, n);
    k_fill<<<eBlk, TPB>>>(src, dst, cnt, bucket, E);
    k_dinv<<<nBlk, TPB>>>(cnt, dinv, n);

    // Transpose + tf32-round all weights in one launch
    k_transpose3<<<dim3(4, 4, 3), dim3(32, 8)>>>(W1, W2, W3, Wt);

    // Conv 1: x -> A   (A fragments RNA-rounded in-register)
    k_gemm_tc<true><<<gemmBlk, 256, GEMM_SMEM_BYTES>>>(x, Wt, dinv, H, n);
    k_pull<<<pullBlk, TPB>>>(bucket, cnt, dinv, H, b1, A, n);

    // Conv 2: A -> B   (A already tf32-rounded by k_pull)
    k_gemm_tc<false><<<gemmBlk, 256, GEMM_SMEM_BYTES>>>(A, Wt + DIM * DIM, dinv, H, n);
    k_pull<<<pullBlk, TPB>>>(bucket, cnt, dinv, H, b2, B, n);

    // Conv 3: B -> A
    k_gemm_tc<false><<<gemmBlk, 256, GEMM_SMEM_BYTES>>>(B, Wt + 2 * DIM * DIM, dinv, H, n);
    k_pull<<<pullBlk, TPB>>>(bucket, cnt, dinv, H, b3, A, n);

    // Regressor on targets
    k_regress<<<regBlk, TPB>>>(A, tgt, Wr, br, out, ntgt);
}

// round 9
// speedup vs baseline: 1.0686x; 1.0367x over previous
#include <cuda_runtime.h>
#include <cuda_bf16.h>
#include <cstdint>

// Problem constants (fixed by the dataset)
#define N_NODES 50000
#define N_EDGES 800000
#define DIM     128
#define OUTD    12
#define CAP     128          // per-node in-edge bucket capacity (Poisson(16) degree)

// ---------------------------------------------------------------------------
// Device scratch (no allocations allowed)
// ---------------------------------------------------------------------------
__device__ float g_H[N_NODES * DIM];        // GEMM output, pre-scaled by dinv
__device__ float g_A[N_NODES * DIM];        // ping (tf32-rounded activations)
__device__ float g_B[N_NODES * DIM];        // pong
__device__ float g_Wt[3 * DIM * DIM];       // transposed + tf32-rounded weights
__device__ float g_dinv[N_NODES];
__device__ int   g_cnt[N_NODES];
__device__ int   g_bucket[N_NODES * CAP];   // in-edge src lists per dst

__device__ __forceinline__ uint32_t f2tf32(float f) {
    uint32_t u;
    asm("cvt.rna.tf32.f32 %0, %1;" : "=r"(u) : "f"(f));
    return u;
}

// ---------------------------------------------------------------------------
// Fused precompute: blocks 0..47 transpose+round weights, rest zero cnt.
// ---------------------------------------------------------------------------
__global__ void k_pre(const float* __restrict__ W1, const float* __restrict__ W2,
                      const float* __restrict__ W3, float* __restrict__ Wt,
                      int* __restrict__ cnt, int n) {
    int b = blockIdx.x;
    int t = threadIdx.x;
    if (b < 48) {
        __shared__ float tile[32][33];
        int bz = b >> 4, rem = b & 15, bx = rem & 3, by = rem >> 2;
        const float* W = (bz == 0) ? W1 : (bz == 1) ? W2 : W3;
        float* dst = Wt + (size_t)bz * DIM * DIM;
        int tx = t & 31, ty = t >> 5;
        int x = bx * 32 + tx, y = by * 32 + ty;
#pragma unroll
        for (int j = 0; j < 32; j += 8)
            tile[ty + j][tx] = W[(y + j) * DIM + x];
        __syncthreads();
        x = by * 32 + tx; y = bx * 32 + ty;
#pragma unroll
        for (int j = 0; j < 32; j += 8)
            dst[(y + j) * DIM + x] = __uint_as_float(f2tf32(tile[tx][ty + j]));
    } else {
        int i = (b - 48) * 256 + t;
        if (i < n) cnt[i] = 0;
    }
}

__global__ void k_fill(const int* __restrict__ src, const int* __restrict__ dst,
                       int* cnt, int* bucket, int E) {
    int e = blockIdx.x * blockDim.x + threadIdx.x;
    if (e >= E) return;
    int d = dst[e];
    int pos = atomicAdd(&cnt[d], 1);
    if (pos < CAP) bucket[(size_t)d * CAP + pos] = src[e];
}

__global__ void k_dinv(const int* __restrict__ cnt, float* dinv, int n) {
    int i = blockIdx.x * blockDim.x + threadIdx.x;
    if (i < n) dinv[i] = rsqrtf(1.0f + (float)cnt[i]);   // +1 = self loop
}

// ---------------------------------------------------------------------------
// tf32 tensor-core GEMM, B-resident / X-streamed.
// H'[r] = dinv[r] * (X[r] @ W).  CTA: 128 rows x 128 cols.
// All of W^T (4 K-chunks, 72KB) staged once; X double-buffered (2x18KB).
// 8 warps in 4x2 grid; warp tile 32x64.  2 CTAs/SM.
// CVTA=true: RNA-round A fragments in-register (layer 1 only).
// ---------------------------------------------------------------------------
#define CLD 36                      // chunk row stride (floats): 32 + 4 pad
#define CHUNK (DIM * CLD)           // 4608 u32 per chunk
#define GEMM_SMEM_BYTES (6 * CHUNK * 4)   // 2 X bufs + 4 B chunks = 110592 B

__device__ __forceinline__ uint32_t smem_u32(const void* p) {
    uint32_t a;
    asm("{ .reg .u64 t; cvta.to.shared.u64 t, %1; cvt.u32.u64 %0, t; }" : "=r"(a) : "l"(p));
    return a;
}

__device__ __forceinline__ void mma_tf32(float* d, const uint32_t* a,
                                         uint32_t b0, uint32_t b1) {
    asm volatile(
        "mma.sync.aligned.m16n8k8.row.col.f32.tf32.tf32.f32 "
        "{%0,%1,%2,%3}, {%4,%5,%6,%7}, {%8,%9}, {%0,%1,%2,%3};"
        : "+f"(d[0]), "+f"(d[1]), "+f"(d[2]), "+f"(d[3])
        : "r"(a[0]), "r"(a[1]), "r"(a[2]), "r"(a[3]), "r"(b0), "r"(b1));
}

template <bool CVTA>
__global__ void __launch_bounds__(256, 2) k_gemm_tc(
    const float* __restrict__ X, const float* __restrict__ Bt,
    const float* __restrict__ dinv, float* __restrict__ H, int n) {
    extern __shared__ uint32_t smem[];
    const int tid  = threadIdx.x;
    const int row0 = blockIdx.x * 128;
    const uint32_t sbase = smem_u32(smem);

    // Stage X K-chunk c into buffer c&1 (1024 float4s over 256 threads).
    auto stage_x = [&](int c) {
        const uint32_t xb = sbase + (uint32_t)(c & 1) * (CHUNK * 4);
        const float4* X4 = (const float4*)X;
#pragma unroll
        for (int i = 0; i < 4; i++) {
            int idx = tid + i * 256;
            int r = idx >> 3, c4 = idx & 7;
            uint32_t off = (uint32_t)(r * CLD + c4 * 4) * 4;
            const float4* xsrc = X4 + ((size_t)(row0 + r) * 32 + c * 8 + c4);
            int vs = (row0 + r < n) ? 16 : 0;
            asm volatile("cp.async.cg.shared.global [%0], [%1], 16, %2;"
                         :: "r"(xb + off), "l"(xsrc), "r"(vs));
        }
    };
    // Stage B K-chunk c into its resident slot (2+c).
    auto stage_b = [&](int c) {
        const uint32_t bb = sbase + (uint32_t)(2 + c) * (CHUNK * 4);
        const float4* B4 = (const float4*)Bt;
#pragma unroll
        for (int i = 0; i < 4; i++) {
            int idx = tid + i * 256;
            int r = idx >> 3, c4 = idx & 7;
            uint32_t off = (uint32_t)(r * CLD + c4 * 4) * 4;
            const float4* bsrc = B4 + ((size_t)r * 32 + c * 8 + c4);
            asm volatile("cp.async.cg.shared.global [%0], [%1], 16;"
                         :: "r"(bb + off), "l"(bsrc));
        }
    };

    // Group 0: all of B + X chunk 0.  Group 1: X chunk 1.
    stage_b(0); stage_b(1); stage_b(2); stage_b(3);
    stage_x(0);
    asm volatile("cp.async.commit_group;" ::: "memory");
    stage_x(1);
    asm volatile("cp.async.commit_group;" ::: "memory");

    const int warp = tid >> 5;
    const int lane = tid & 31;
    const int wm   = warp & 3;        // m-tile: rows wm*32 .. wm*32+31
    const int wn   = warp >> 2;       // n-tile: cols wn*64 .. wn*64+63
    const int g    = lane >> 2;       // group id (0..7)
    const int tg   = lane & 3;        // thread-in-group (0..3)

    float acc[2][8][4];
#pragma unroll
    for (int mt = 0; mt < 2; mt++)
#pragma unroll
        for (int nt = 0; nt < 8; nt++)
#pragma unroll
            for (int q = 0; q < 4; q++) acc[mt][nt][q] = 0.f;

#pragma unroll
    for (int c = 0; c < 4; c++) {
        if (c < 3) asm volatile("cp.async.wait_group 1;" ::: "memory");
        else       asm volatile("cp.async.wait_group 0;" ::: "memory");
        __syncthreads();

        const uint32_t* Xs = smem + (c & 1) * CHUNK;
        const uint32_t* Bs = smem + (2 + c) * CHUNK;

#pragma unroll
        for (int ks = 0; ks < 4; ks++) {
            const int k0 = ks * 8;
            uint32_t a[2][4];
#pragma unroll
            for (int mt = 0; mt < 2; mt++) {
                int r0 = wm * 32 + mt * 16;
                a[mt][0] = Xs[(r0 + g) * CLD + k0 + tg];
                a[mt][1] = Xs[(r0 + 8 + g) * CLD + k0 + tg];
                a[mt][2] = Xs[(r0 + g) * CLD + k0 + tg + 4];
                a[mt][3] = Xs[(r0 + 8 + g) * CLD + k0 + tg + 4];
                if (CVTA) {
#pragma unroll
                    for (int q = 0; q < 4; q++)
                        a[mt][q] = f2tf32(__uint_as_float(a[mt][q]));
                }
            }
#pragma unroll
            for (int nt = 0; nt < 8; nt++) {
                int c0 = wn * 64 + nt * 8;
                uint32_t b0 = Bs[(c0 + g) * CLD + k0 + tg];
                uint32_t b1 = Bs[(c0 + g) * CLD + k0 + tg + 4];
                mma_tf32(acc[0][nt], a[0], b0, b1);
                mma_tf32(acc[1][nt], a[1], b0, b1);
            }
        }
        __syncthreads();
        if (c + 2 < 4) {
            stage_x(c + 2);
            asm volatile("cp.async.commit_group;" ::: "memory");
        }
    }

    // Epilogue: scale by dinv[row], float2 stores.
#pragma unroll
    for (int mt = 0; mt < 2; mt++) {
        int r0 = row0 + wm * 32 + mt * 16 + g;
        int r1 = r0 + 8;
        float dv0 = (r0 < n) ? dinv[r0] : 0.f;
        float dv1 = (r1 < n) ? dinv[r1] : 0.f;
#pragma unroll
        for (int nt = 0; nt < 8; nt++) {
            int col = wn * 64 + nt * 8 + tg * 2;
            if (r0 < n) {
                float2 o = make_float2(acc[mt][nt][0] * dv0, acc[mt][nt][1] * dv0);
                *(float2*)&H[(size_t)r0 * DIM + col] = o;
            }
            if (r1 < n) {
                float2 o = make_float2(acc[mt][nt][2] * dv1, acc[mt][nt][3] * dv1);
                *(float2*)&H[(size_t)r1 * DIM + col] = o;
            }
        }
    }
}

// ---------------------------------------------------------------------------
// Pull aggregation: one warp per destination node, fp32, 4-way ILP.
// OUT[v] = rna_tf32(relu(bias + dinv[v] * (H'[v] + sum_{s in in(v)} H'[s])))
// ---------------------------------------------------------------------------
__global__ void k_pull(const int* __restrict__ bucket, const int* __restrict__ cnt,
                       const float* __restrict__ dinv, const float* __restrict__ H,
                       const float* __restrict__ bias, float* __restrict__ OUT, int n) {
    int warp = (blockIdx.x * blockDim.x + threadIdx.x) >> 5;
    int lane = threadIdx.x & 31;
    if (warp >= n) return;
    const int v   = warp;
    int deg = cnt[v];
    if (deg > CAP) deg = CAP;
    const int* bk = bucket + (size_t)v * CAP;
    const float4* H4 = (const float4*)H;

    float4 acc0 = H4[(size_t)v * 32 + lane];   // self-loop term
    float4 acc1 = make_float4(0.f, 0.f, 0.f, 0.f);
    float4 acc2 = make_float4(0.f, 0.f, 0.f, 0.f);
    float4 acc3 = make_float4(0.f, 0.f, 0.f, 0.f);

    for (int base = 0; base < deg; base += 32) {
        int m = deg - base; if (m > 32) m = 32;
        int myS = (lane < m) ? bk[base + lane] : 0;
        int i = 0;
        for (; i + 4 <= m; i += 4) {
            int s0 = __shfl_sync(0xffffffff, myS, i);
            int s1 = __shfl_sync(0xffffffff, myS, i + 1);
            int s2 = __shfl_sync(0xffffffff, myS, i + 2);
            int s3 = __shfl_sync(0xffffffff, myS, i + 3);
            float4 h0 = H4[(size_t)s0 * 32 + lane];
            float4 h1 = H4[(size_t)s1 * 32 + lane];
            float4 h2 = H4[(size_t)s2 * 32 + lane];
            float4 h3 = H4[(size_t)s3 * 32 + lane];
            acc0.x += h0.x; acc0.y += h0.y; acc0.z += h0.z; acc0.w += h0.w;
            acc1.x += h1.x; acc1.y += h1.y; acc1.z += h1.z; acc1.w += h1.w;
            acc2.x += h2.x; acc2.y += h2.y; acc2.z += h2.z; acc2.w += h2.w;
            acc3.x += h3.x; acc3.y += h3.y; acc3.z += h3.z; acc3.w += h3.w;
        }
        for (; i < m; i++) {
            int s0 = __shfl_sync(0xffffffff, myS, i);
            float4 h0 = H4[(size_t)s0 * 32 + lane];
            acc0.x += h0.x; acc0.y += h0.y; acc0.z += h0.z; acc0.w += h0.w;
        }
    }

    float dv = dinv[v];
    const float4 bb = ((const float4*)bias)[lane];
    float sx = (acc0.x + acc1.x) + (acc2.x + acc3.x);
    float sy = (acc0.y + acc1.y) + (acc2.y + acc3.y);
    float sz = (acc0.z + acc1.z) + (acc2.z + acc3.z);
    float sw = (acc0.w + acc1.w) + (acc2.w + acc3.w);
    float4 o;
    o.x = __uint_as_float(f2tf32(fmaxf(fmaf(sx, dv, bb.x), 0.f)));
    o.y = __uint_as_float(f2tf32(fmaxf(fmaf(sy, dv, bb.y), 0.f)));
    o.z = __uint_as_float(f2tf32(fmaxf(fmaf(sz, dv, bb.z), 0.f)));
    o.w = __uint_as_float(f2tf32(fmaxf(fmaf(sw, dv, bb.w), 0.f)));
    ((float4*)OUT)[(size_t)v * 32 + lane] = o;
}

// ---------------------------------------------------------------------------
// Regressor: pred[t] = A[target[t]] @ Wr[128 x 12] + br   (A already relu'd)
// ---------------------------------------------------------------------------
__global__ void k_regress(const float* __restrict__ H, const int* __restrict__ tgt,
                          const float* __restrict__ Wr, const float* __restrict__ br,
                          float* __restrict__ out, int ntgt) {
    __shared__ float Wrs[DIM * OUTD];
    __shared__ float brs[OUTD];
    int tid = threadIdx.x;
    for (int i = tid; i < DIM * OUTD; i += blockDim.x) Wrs[i] = Wr[i];
    if (tid < OUTD) brs[tid] = br[tid];
    __syncthreads();

    int warp = (blockIdx.x * blockDim.x + tid) >> 5;
    int lane = tid & 31;
    if (warp >= ntgt) return;
    int t = tgt[warp];
    float4 v = ((const float4*)H)[(size_t)t * 32 + lane];
    int k0 = lane * 4;
#pragma unroll
    for (int o = 0; o < OUTD; o++) {
        float p = v.x * Wrs[(k0 + 0) * OUTD + o]
                + v.y * Wrs[(k0 + 1) * OUTD + o]
                + v.z * Wrs[(k0 + 2) * OUTD + o]
                + v.w * Wrs[(k0 + 3) * OUTD + o];
#pragma unroll
        for (int off = 16; off > 0; off >>= 1)
            p += __shfl_xor_sync(0xffffffff, p, off);
        if (lane == 0) out[warp * OUTD + o] = p + brs[o];
    }
}

// ---------------------------------------------------------------------------
// Launch
// ---------------------------------------------------------------------------
extern "C" void kernel_launch(void* const* d_in, const int* in_sizes, int n_in,
                              void* d_out, int out_size) {
    const float* x    = (const float*)d_in[0];
    const int*   ei   = (const int*)d_in[1];
    const int*   tgt  = (const int*)d_in[2];
    const float* W1   = (const float*)d_in[3];
    const float* b1   = (const float*)d_in[4];
    const float* W2   = (const float*)d_in[5];
    const float* b2   = (const float*)d_in[6];
    const float* W3   = (const float*)d_in[7];
    const float* b3   = (const float*)d_in[8];
    const float* Wr   = (const float*)d_in[9];
    const float* br   = (const float*)d_in[10];
    float* out = (float*)d_out;

    const int n    = in_sizes[0] / DIM;
    const int E    = in_sizes[1] / 2;
    const int ntgt = in_sizes[2];
    const int* src = ei;
    const int* dst = ei + E;

    float *H, *A, *B, *Wt, *dinv;
    int *cnt, *bucket;
    cudaGetSymbolAddress((void**)&H,      g_H);
    cudaGetSymbolAddress((void**)&A,      g_A);
    cudaGetSymbolAddress((void**)&B,      g_B);
    cudaGetSymbolAddress((void**)&Wt,     g_Wt);
    cudaGetSymbolAddress((void**)&dinv,   g_dinv);
    cudaGetSymbolAddress((void**)&cnt,    g_cnt);
    cudaGetSymbolAddress((void**)&bucket, g_bucket);

    cudaFuncSetAttribute(k_gemm_tc<true>, cudaFuncAttributeMaxDynamicSharedMemorySize,
                         GEMM_SMEM_BYTES);
    cudaFuncSetAttribute(k_gemm_tc<false>, cudaFuncAttributeMaxDynamicSharedMemorySize,
                         GEMM_SMEM_BYTES);

    const int TPB = 256;
    const int nBlk    = (n + TPB - 1) / TPB;
    const int eBlk    = (E + TPB - 1) / TPB;
    const int gemmBlk = (n + 127) / 128;
    const int pullBlk = ((n * 32) + TPB - 1) / TPB;
    const int regBlk  = ((ntgt * 32) + TPB - 1) / TPB;

    // 1: transpose+round weights, zero counts (fused)
    k_pre<<<48 + nBlk, TPB>>>(W1, W2, W3, Wt, cnt, n);
    // 2-3: buckets + dinv
    k_fill<<<eBlk, TPB>>>(src, dst, cnt, bucket, E);
    k_dinv<<<nBlk, TPB>>>(cnt, dinv, n);

    // Conv 1: x -> A   (launch #4 = first GEMM, lands in the ncu sample slot)
    k_gemm_tc<true><<<gemmBlk, 256, GEMM_SMEM_BYTES>>>(x, Wt, dinv, H, n);
    k_pull<<<pullBlk, TPB>>>(bucket, cnt, dinv, H, b1, A, n);

    // Conv 2: A -> B
    k_gemm_tc<false><<<gemmBlk, 256, GEMM_SMEM_BYTES>>>(A, Wt + DIM * DIM, dinv, H, n);
    k_pull<<<pullBlk, TPB>>>(bucket, cnt, dinv, H, b2, B, n);

    // Conv 3: B -> A
    k_gemm_tc<false><<<gemmBlk, 256, GEMM_SMEM_BYTES>>>(B, Wt + 2 * DIM * DIM, dinv, H, n);
    k_pull<<<pullBlk, TPB>>>(bucket, cnt, dinv, H, b3, A, n);

    // Regressor on targets
    k_regress<<<regBlk, TPB>>>(A, tgt, Wr, br, out, ntgt);
}